// round 15
// baseline (speedup 1.0000x reference)
#include <cuda_runtime.h>
#include <cstdint>
#include <math.h>

// Problem dims
#define Bb 8
#define Tt 4096
#define Cc 512
#define NCHUNK 256
#define LCHUNK 16   // Tt / NCHUNK

// Scratch (device globals: no runtime allocation allowed)
__device__ __align__(256) float g_y[Bb * Tt * Cc];      // 64 MB intermediate y (tf32-rounded)
__device__ __align__(256) float g_A[Bb * NCHUNK * Cc];  // chunk sums -> exclusive prefix
__device__ __align__(256) float g_W[Cc * Cc];           // tf32-rounded weights

__device__ __forceinline__ float tf32_rn(float f) {
    uint32_t u;
    asm("cvt.rna.tf32.f32 %0, %1;" : "=r"(u) : "f"(f));
    return __uint_as_float(u);
}

// ---------------------------------------------------------------------------
// Kernel 1: per-chunk absolutely-weighted sums  A[b,k,c] = sum_j d^(t0+j) x
// First 512 blocks also convert one float4 of W to tf32 per thread.
// ---------------------------------------------------------------------------
__global__ void __launch_bounds__(128) chunk_sum_kernel(
    const float* __restrict__ x, const float* __restrict__ logd,
    const float* __restrict__ W)
{
    const int b = blockIdx.x / NCHUNK;
    const int k = blockIdx.x % NCHUNK;
    const int c = threadIdx.x * 4;

    if (blockIdx.x < 512) {
        const int i = (blockIdx.x * 128 + threadIdx.x) * 4;
        float4 v = *reinterpret_cast<const float4*>(W + i);
        v.x = tf32_rn(v.x); v.y = tf32_rn(v.y); v.z = tf32_rn(v.z); v.w = tf32_rn(v.w);
        *reinterpret_cast<float4*>(&g_W[i]) = v;
    }

    float4 ld4 = *reinterpret_cast<const float4*>(logd + c);
    const float d0 = 1.0f / (1.0f + expf(-ld4.x));
    const float d1 = 1.0f / (1.0f + expf(-ld4.y));
    const float d2 = 1.0f / (1.0f + expf(-ld4.z));
    const float d3 = 1.0f / (1.0f + expf(-ld4.w));

    const float ft0 = (float)(k * LCHUNK);
    float w0 = exp2f(ft0 * log2f(d0));
    float w1 = exp2f(ft0 * log2f(d1));
    float w2 = exp2f(ft0 * log2f(d2));
    float w3 = exp2f(ft0 * log2f(d3));

    const float* xp = x + ((size_t)b * Tt + (size_t)k * LCHUNK) * Cc + c;

    float a0 = 0.f, a1 = 0.f, a2 = 0.f, a3 = 0.f;
#pragma unroll
    for (int j = 0; j < LCHUNK; ++j) {
        float4 v = *reinterpret_cast<const float4*>(xp + (size_t)j * Cc);
        a0 += w0 * v.x;
        a1 += w1 * v.y;
        a2 += w2 * v.z;
        a3 += w3 * v.w;
        w0 *= d0; w1 *= d1; w2 *= d2; w3 *= d3;
    }

    float4 r; r.x = a0; r.y = a1; r.z = a2; r.w = a3;
    *reinterpret_cast<float4*>(&g_A[((size_t)b * NCHUNK + k) * Cc + c]) = r;
}

// ---------------------------------------------------------------------------
// Kernel 1b: in-place exclusive prefix over chunks of g_A.
// One thread per (b,c): serial cumsum over k (same add order as before).
// ---------------------------------------------------------------------------
__global__ void __launch_bounds__(128) prefix_kernel()
{
    const int gid = blockIdx.x * 128 + threadIdx.x;  // 0..4095
    const int b = gid >> 9;
    const int c = gid & 511;
    float* Ap = g_A + (size_t)b * NCHUNK * Cc + c;
    float P = 0.f;
#pragma unroll 8
    for (int k = 0; k < NCHUNK; ++k) {
        const float v = Ap[(size_t)k * Cc];
        Ap[(size_t)k * Cc] = P;
        P += v;
    }
}

// ---------------------------------------------------------------------------
// Kernel 2: local rescan; y = d^(T-1-t) * (P + local sum), tf32-rounded.
// P comes from the exclusive-prefix g_A row.
// ---------------------------------------------------------------------------
__global__ void __launch_bounds__(128) apply_kernel(
    const float* __restrict__ x, const float* __restrict__ logd)
{
    const int b = blockIdx.x / NCHUNK;
    const int k = blockIdx.x % NCHUNK;
    const int c = threadIdx.x * 4;

    float4 ld4 = *reinterpret_cast<const float4*>(logd + c);
    const float d0 = 1.0f / (1.0f + expf(-ld4.x));
    const float d1 = 1.0f / (1.0f + expf(-ld4.y));
    const float d2 = 1.0f / (1.0f + expf(-ld4.z));
    const float d3 = 1.0f / (1.0f + expf(-ld4.w));
    const float l20 = log2f(d0), l21 = log2f(d1), l22 = log2f(d2), l23 = log2f(d3);

    const float4 Pv = *reinterpret_cast<const float4*>(
        g_A + ((size_t)b * NCHUNK + k) * Cc + c);

    const int t0 = k * LCHUNK;
    const float ft0 = (float)t0;
    float w0 = exp2f(ft0 * l20);
    float w1 = exp2f(ft0 * l21);
    float w2 = exp2f(ft0 * l22);
    float w3 = exp2f(ft0 * l23);

    const float eb0 = (float)(Tt - 1 - t0) * l20;
    const float eb1 = (float)(Tt - 1 - t0) * l21;
    const float eb2 = (float)(Tt - 1 - t0) * l22;
    const float eb3 = (float)(Tt - 1 - t0) * l23;
    const float ee0 = (float)(Tt - 1 - t0 - (LCHUNK - 1)) * l20;
    const float ee1 = (float)(Tt - 1 - t0 - (LCHUNK - 1)) * l21;
    const float ee2 = (float)(Tt - 1 - t0 - (LCHUNK - 1)) * l22;
    const float ee3 = (float)(Tt - 1 - t0 - (LCHUNK - 1)) * l23;
    const bool ex0 = (eb0 < -100.f) && (ee0 > -140.f);
    const bool ex1 = (eb1 < -100.f) && (ee1 > -140.f);
    const bool ex2 = (eb2 < -100.f) && (ee2 > -140.f);
    const bool ex3 = (eb3 < -100.f) && (ee3 > -140.f);
    const bool anyex = ex0 | ex1 | ex2 | ex3;

    float pt0 = exp2f(eb0), pt1 = exp2f(eb1), pt2 = exp2f(eb2), pt3 = exp2f(eb3);
    const float i0 = 1.0f / d0, i1 = 1.0f / d1, i2 = 1.0f / d2, i3 = 1.0f / d3;

    float S0 = Pv.x, S1 = Pv.y, S2 = Pv.z, S3 = Pv.w;

    const float* xp = x + ((size_t)b * Tt + t0) * Cc + c;
    float* yp = g_y + ((size_t)b * Tt + t0) * Cc + c;

    if (!anyex) {
#pragma unroll
        for (int j = 0; j < LCHUNK; ++j) {
            float4 v = *reinterpret_cast<const float4*>(xp + (size_t)j * Cc);
            S0 += w0 * v.x; w0 *= d0;
            S1 += w1 * v.y; w1 *= d1;
            S2 += w2 * v.z; w2 *= d2;
            S3 += w3 * v.w; w3 *= d3;
            float4 r;
            r.x = tf32_rn(pt0 * S0); r.y = tf32_rn(pt1 * S1);
            r.z = tf32_rn(pt2 * S2); r.w = tf32_rn(pt3 * S3);
            pt0 *= i0; pt1 *= i1; pt2 *= i2; pt3 *= i3;
            *reinterpret_cast<float4*>(yp + (size_t)j * Cc) = r;
        }
    } else {
        for (int j = 0; j < LCHUNK; ++j) {
            const float tj = (float)(Tt - 1 - t0 - j);
            pt0 = ex0 ? exp2f(tj * l20) : pt0;
            pt1 = ex1 ? exp2f(tj * l21) : pt1;
            pt2 = ex2 ? exp2f(tj * l22) : pt2;
            pt3 = ex3 ? exp2f(tj * l23) : pt3;
            float4 v = *reinterpret_cast<const float4*>(xp + (size_t)j * Cc);
            S0 += w0 * v.x; w0 *= d0;
            S1 += w1 * v.y; w1 *= d1;
            S2 += w2 * v.z; w2 *= d2;
            S3 += w3 * v.w; w3 *= d3;
            float4 r;
            r.x = tf32_rn(pt0 * S0); r.y = tf32_rn(pt1 * S1);
            r.z = tf32_rn(pt2 * S2); r.w = tf32_rn(pt3 * S3);
            pt0 = ex0 ? pt0 : pt0 * i0;
            pt1 = ex1 ? pt1 : pt1 * i1;
            pt2 = ex2 ? pt2 : pt2 * i2;
            pt3 = ex3 ? pt3 : pt3 * i3;
            *reinterpret_cast<float4*>(yp + (size_t)j * Cc) = r;
        }
    }
}

// ---------------------------------------------------------------------------
// Kernel 3: tf32 tensor-core GEMM via mma.sync + ldmatrix.
// out = y @ W^T + bias. CTA tile 64x128x16, 128 threads (4 warps 2m x 2n,
// warp tile 32x64), 4 CTAs/SM (4 independent barrier domains),
// 3-stage cp.async pipeline, LDSM.x4 loads, pitch 20 (conflict-free).
// ---------------------------------------------------------------------------
#define BM 64
#define BN 128
#define KC 16
#define NCHK (Cc / KC)           // 32
#define PITCH 20                 // floats per smem row (16 + 4 pad)
#define A_ST_FLOATS (BM * PITCH) // 1280
#define B_ST_FLOATS (BN * PITCH) // 2560
#define STAGE_FLOATS (A_ST_FLOATS + B_ST_FLOATS)  // 3840
#define NSTAGE 3
#define SMEM_TOTAL (NSTAGE * STAGE_FLOATS * 4)    // 46080 B

__device__ __forceinline__ void mma_tf32(float* d, const uint32_t* a, const uint32_t* b) {
    asm volatile(
        "mma.sync.aligned.m16n8k8.row.col.f32.tf32.tf32.f32 "
        "{%0,%1,%2,%3}, {%4,%5,%6,%7}, {%8,%9}, {%0,%1,%2,%3};"
        : "+f"(d[0]), "+f"(d[1]), "+f"(d[2]), "+f"(d[3])
        : "r"(a[0]), "r"(a[1]), "r"(a[2]), "r"(a[3]), "r"(b[0]), "r"(b[1]));
}

__device__ __forceinline__ void ldsm_x4(uint32_t* r, uint32_t saddr) {
    asm volatile(
        "ldmatrix.sync.aligned.m8n8.x4.shared.b16 {%0,%1,%2,%3}, [%4];"
        : "=r"(r[0]), "=r"(r[1]), "=r"(r[2]), "=r"(r[3]) : "r"(saddr));
}

__global__ void __launch_bounds__(128, 4) gemm_mma_kernel(
    const float* __restrict__ bias, float* __restrict__ out)
{
    extern __shared__ __align__(128) float smem[];

    const int tid = threadIdx.x;
    const int wid = tid >> 5;
    const int lane = tid & 31;
    const int q = lane >> 2;   // 0..7
    const int cq = lane & 3;   // 0..3

    const int bm = blockIdx.x >> 2;   // 0..511
    const int bn = blockIdx.x & 3;    // 0..3
    const int wm = wid >> 1;          // 0..1  (32-row blocks)
    const int wn = wid & 1;           // 0..1  (64-col blocks)

    const float* Abase = g_y + (size_t)(bm * BM) * Cc;
    const float* Bbase = g_W + (size_t)(bn * BN) * Cc;

    const uint32_t smemS = (uint32_t)__cvta_generic_to_shared(smem);

    // ldmatrix per-lane addresses (A: {(m0,k8),(m0+8,k8),(m0,k8+4),(m0+8,k8+4)};
    //  B pair p: {(n0,k8),(n0,k8+4),(n0+8,k8),(n0+8,k8+4)})
    const int rowA = (lane & 7) + ((lane >> 3) & 1) * 8;
    const int colA = (lane >> 4) * 4;
    const int rowB = (lane & 7) + (lane >> 4) * 8;
    const int colB = ((lane >> 3) & 1) * 4;

    const uint32_t aLane = (uint32_t)(((wm * 32 + rowA) * PITCH + colA) * 4);
    const uint32_t bLane = (uint32_t)((A_ST_FLOATS + (wn * 64 + rowB) * PITCH + colB) * 4);

    // cp.async issue helper: 768 16B-segments per chunk (A:256, B:512)
    auto issue_chunk = [&](int ch) {
        float* stg = smem + (ch % NSTAGE) * STAGE_FLOATS;
        const int kof = ch * KC;
#pragma unroll
        for (int i = 0; i < 6; ++i) {
            const int u = tid + i * 128;
            const float* src;
            float* dst;
            if (u < 256) {
                const int row = u >> 2, seg = u & 3;
                src = Abase + (size_t)row * Cc + kof + seg * 4;
                dst = stg + row * PITCH + seg * 4;
            } else {
                const int v = u - 256;
                const int row = v >> 2, seg = v & 3;
                src = Bbase + (size_t)row * Cc + kof + seg * 4;
                dst = stg + A_ST_FLOATS + row * PITCH + seg * 4;
            }
            uint32_t daddr = (uint32_t)__cvta_generic_to_shared(dst);
            asm volatile("cp.async.cg.shared.global [%0], [%1], 16;"
                         :: "r"(daddr), "l"(src) : "memory");
        }
        asm volatile("cp.async.commit_group;" ::: "memory");
    };

    // Prologue: chunks 0,1
    issue_chunk(0);
    issue_chunk(1);

    float acc[2][8][4];
#pragma unroll
    for (int mt = 0; mt < 2; ++mt)
#pragma unroll
        for (int nt = 0; nt < 8; ++nt)
#pragma unroll
            for (int e = 0; e < 4; ++e) acc[mt][nt][e] = 0.f;

#pragma unroll 1
    for (int ch = 0; ch < NCHK; ++ch) {
        if (ch < NCHK - 1) {
            asm volatile("cp.async.wait_group 1;" ::: "memory");
        } else {
            asm volatile("cp.async.wait_group 0;" ::: "memory");
        }
        __syncthreads();   // chunk ch visible; compute(ch-1) done by all

        if (ch + 2 < NCHK) issue_chunk(ch + 2);

        const uint32_t stS = smemS + (uint32_t)((ch % NSTAGE) * STAGE_FLOATS * 4);
        const uint32_t aBase = stS + aLane;
        const uint32_t bBase = stS + bLane;

#pragma unroll
        for (int ks = 0; ks < 2; ++ks) {
            const uint32_t ko = (uint32_t)(ks * 8 * 4);
            uint32_t a[2][4], b[8][2];
#pragma unroll
            for (int mt = 0; mt < 2; ++mt)
                ldsm_x4(a[mt], aBase + (uint32_t)(mt * 16 * PITCH * 4) + ko);
#pragma unroll
            for (int p = 0; p < 4; ++p)
                ldsm_x4(&b[2 * p][0], bBase + (uint32_t)(p * 16 * PITCH * 4) + ko);
#pragma unroll
            for (int mt = 0; mt < 2; ++mt)
#pragma unroll
                for (int nt = 0; nt < 8; ++nt)
                    mma_tf32(acc[mt][nt], a[mt], b[nt]);
        }
    }

    // Epilogue: bias + store
#pragma unroll
    for (int nt = 0; nt < 8; ++nt) {
        const int col = bn * BN + wn * 64 + nt * 8 + cq * 2;
        const float b0 = __ldg(bias + col);
        const float b1 = __ldg(bias + col + 1);
#pragma unroll
        for (int mt = 0; mt < 2; ++mt) {
            const size_t row0 = (size_t)(bm * BM + wm * 32 + mt * 16 + q);
            float2 v0, v1;
            v0.x = acc[mt][nt][0] + b0; v0.y = acc[mt][nt][1] + b1;
            v1.x = acc[mt][nt][2] + b0; v1.y = acc[mt][nt][3] + b1;
            *reinterpret_cast<float2*>(out + row0 * Cc + col) = v0;
            *reinterpret_cast<float2*>(out + (row0 + 8) * Cc + col) = v1;
        }
    }
}

// ---------------------------------------------------------------------------
extern "C" void kernel_launch(void* const* d_in, const int* in_sizes, int n_in,
                              void* d_out, int out_size)
{
    (void)in_sizes; (void)n_in; (void)out_size;
    const float* x    = (const float*)d_in[0];
    const float* logd = (const float*)d_in[1];
    const float* mixw = (const float*)d_in[2];
    const float* bias = (const float*)d_in[3];
    float* out = (float*)d_out;

    cudaFuncSetAttribute(gemm_mma_kernel, cudaFuncAttributeMaxDynamicSharedMemorySize,
                         SMEM_TOTAL);

    chunk_sum_kernel<<<Bb * NCHUNK, 128>>>(x, logd, mixw);
    prefix_kernel<<<32, 128>>>();
    apply_kernel<<<Bb * NCHUNK, 128>>>(x, logd);
    gemm_mma_kernel<<<2048, 128, SMEM_TOTAL>>>(bias, out);
}

// round 16
// speedup vs baseline: 1.0999x; 1.0999x over previous
#include <cuda_runtime.h>
#include <cstdint>
#include <math.h>

// Problem dims
#define Bb 8
#define Tt 4096
#define Cc 512
#define NCHUNK 256
#define LCHUNK 16   // Tt / NCHUNK

// Scratch (device globals: no runtime allocation allowed)
__device__ __align__(256) float g_y[Bb * Tt * Cc];      // 64 MB intermediate y (tf32-rounded)
__device__ __align__(256) float g_A[Bb * NCHUNK * Cc];  // chunk sums -> exclusive prefix
__device__ __align__(256) float g_W[Cc * Cc];           // tf32-rounded weights

__device__ __forceinline__ float tf32_rn(float f) {
    uint32_t u;
    asm("cvt.rna.tf32.f32 %0, %1;" : "=r"(u) : "f"(f));
    return __uint_as_float(u);
}

// ---------------------------------------------------------------------------
// Kernel 1: per-chunk absolutely-weighted sums  A[b,k,c] = sum_j d^(t0+j) x
// First 512 blocks also convert one float4 of W to tf32 per thread.
// ---------------------------------------------------------------------------
__global__ void __launch_bounds__(128) chunk_sum_kernel(
    const float* __restrict__ x, const float* __restrict__ logd,
    const float* __restrict__ W)
{
    const int b = blockIdx.x / NCHUNK;
    const int k = blockIdx.x % NCHUNK;
    const int c = threadIdx.x * 4;

    if (blockIdx.x < 512) {
        const int i = (blockIdx.x * 128 + threadIdx.x) * 4;
        float4 v = *reinterpret_cast<const float4*>(W + i);
        v.x = tf32_rn(v.x); v.y = tf32_rn(v.y); v.z = tf32_rn(v.z); v.w = tf32_rn(v.w);
        *reinterpret_cast<float4*>(&g_W[i]) = v;
    }

    float4 ld4 = *reinterpret_cast<const float4*>(logd + c);
    const float d0 = 1.0f / (1.0f + expf(-ld4.x));
    const float d1 = 1.0f / (1.0f + expf(-ld4.y));
    const float d2 = 1.0f / (1.0f + expf(-ld4.z));
    const float d3 = 1.0f / (1.0f + expf(-ld4.w));

    const float ft0 = (float)(k * LCHUNK);
    float w0 = exp2f(ft0 * log2f(d0));
    float w1 = exp2f(ft0 * log2f(d1));
    float w2 = exp2f(ft0 * log2f(d2));
    float w3 = exp2f(ft0 * log2f(d3));

    const float* xp = x + ((size_t)b * Tt + (size_t)k * LCHUNK) * Cc + c;

    float a0 = 0.f, a1 = 0.f, a2 = 0.f, a3 = 0.f;
#pragma unroll
    for (int j = 0; j < LCHUNK; ++j) {
        float4 v = *reinterpret_cast<const float4*>(xp + (size_t)j * Cc);
        a0 += w0 * v.x;
        a1 += w1 * v.y;
        a2 += w2 * v.z;
        a3 += w3 * v.w;
        w0 *= d0; w1 *= d1; w2 *= d2; w3 *= d3;
    }

    float4 r; r.x = a0; r.y = a1; r.z = a2; r.w = a3;
    *reinterpret_cast<float4*>(&g_A[((size_t)b * NCHUNK + k) * Cc + c]) = r;
}

// ---------------------------------------------------------------------------
// Kernel 1b: in-place exclusive prefix over chunks of g_A.
// One thread per (b,c): serial cumsum over k (same add order as before).
// ---------------------------------------------------------------------------
__global__ void __launch_bounds__(128) prefix_kernel()
{
    const int gid = blockIdx.x * 128 + threadIdx.x;  // 0..4095
    const int b = gid >> 9;
    const int c = gid & 511;
    float* Ap = g_A + (size_t)b * NCHUNK * Cc + c;
    float P = 0.f;
#pragma unroll 8
    for (int k = 0; k < NCHUNK; ++k) {
        const float v = Ap[(size_t)k * Cc];
        Ap[(size_t)k * Cc] = P;
        P += v;
    }
}

// ---------------------------------------------------------------------------
// Kernel 2: local rescan; y = d^(T-1-t) * (P + local sum), tf32-rounded.
// P comes from the exclusive-prefix g_A row.
// ---------------------------------------------------------------------------
__global__ void __launch_bounds__(128) apply_kernel(
    const float* __restrict__ x, const float* __restrict__ logd)
{
    const int b = blockIdx.x / NCHUNK;
    const int k = blockIdx.x % NCHUNK;
    const int c = threadIdx.x * 4;

    float4 ld4 = *reinterpret_cast<const float4*>(logd + c);
    const float d0 = 1.0f / (1.0f + expf(-ld4.x));
    const float d1 = 1.0f / (1.0f + expf(-ld4.y));
    const float d2 = 1.0f / (1.0f + expf(-ld4.z));
    const float d3 = 1.0f / (1.0f + expf(-ld4.w));
    const float l20 = log2f(d0), l21 = log2f(d1), l22 = log2f(d2), l23 = log2f(d3);

    const float4 Pv = *reinterpret_cast<const float4*>(
        g_A + ((size_t)b * NCHUNK + k) * Cc + c);

    const int t0 = k * LCHUNK;
    const float ft0 = (float)t0;
    float w0 = exp2f(ft0 * l20);
    float w1 = exp2f(ft0 * l21);
    float w2 = exp2f(ft0 * l22);
    float w3 = exp2f(ft0 * l23);

    const float eb0 = (float)(Tt - 1 - t0) * l20;
    const float eb1 = (float)(Tt - 1 - t0) * l21;
    const float eb2 = (float)(Tt - 1 - t0) * l22;
    const float eb3 = (float)(Tt - 1 - t0) * l23;
    const float ee0 = (float)(Tt - 1 - t0 - (LCHUNK - 1)) * l20;
    const float ee1 = (float)(Tt - 1 - t0 - (LCHUNK - 1)) * l21;
    const float ee2 = (float)(Tt - 1 - t0 - (LCHUNK - 1)) * l22;
    const float ee3 = (float)(Tt - 1 - t0 - (LCHUNK - 1)) * l23;
    const bool ex0 = (eb0 < -100.f) && (ee0 > -140.f);
    const bool ex1 = (eb1 < -100.f) && (ee1 > -140.f);
    const bool ex2 = (eb2 < -100.f) && (ee2 > -140.f);
    const bool ex3 = (eb3 < -100.f) && (ee3 > -140.f);
    const bool anyex = ex0 | ex1 | ex2 | ex3;

    float pt0 = exp2f(eb0), pt1 = exp2f(eb1), pt2 = exp2f(eb2), pt3 = exp2f(eb3);
    const float i0 = 1.0f / d0, i1 = 1.0f / d1, i2 = 1.0f / d2, i3 = 1.0f / d3;

    float S0 = Pv.x, S1 = Pv.y, S2 = Pv.z, S3 = Pv.w;

    const float* xp = x + ((size_t)b * Tt + t0) * Cc + c;
    float* yp = g_y + ((size_t)b * Tt + t0) * Cc + c;

    if (!anyex) {
#pragma unroll
        for (int j = 0; j < LCHUNK; ++j) {
            float4 v = *reinterpret_cast<const float4*>(xp + (size_t)j * Cc);
            S0 += w0 * v.x; w0 *= d0;
            S1 += w1 * v.y; w1 *= d1;
            S2 += w2 * v.z; w2 *= d2;
            S3 += w3 * v.w; w3 *= d3;
            float4 r;
            r.x = tf32_rn(pt0 * S0); r.y = tf32_rn(pt1 * S1);
            r.z = tf32_rn(pt2 * S2); r.w = tf32_rn(pt3 * S3);
            pt0 *= i0; pt1 *= i1; pt2 *= i2; pt3 *= i3;
            *reinterpret_cast<float4*>(yp + (size_t)j * Cc) = r;
        }
    } else {
        for (int j = 0; j < LCHUNK; ++j) {
            const float tj = (float)(Tt - 1 - t0 - j);
            pt0 = ex0 ? exp2f(tj * l20) : pt0;
            pt1 = ex1 ? exp2f(tj * l21) : pt1;
            pt2 = ex2 ? exp2f(tj * l22) : pt2;
            pt3 = ex3 ? exp2f(tj * l23) : pt3;
            float4 v = *reinterpret_cast<const float4*>(xp + (size_t)j * Cc);
            S0 += w0 * v.x; w0 *= d0;
            S1 += w1 * v.y; w1 *= d1;
            S2 += w2 * v.z; w2 *= d2;
            S3 += w3 * v.w; w3 *= d3;
            float4 r;
            r.x = tf32_rn(pt0 * S0); r.y = tf32_rn(pt1 * S1);
            r.z = tf32_rn(pt2 * S2); r.w = tf32_rn(pt3 * S3);
            pt0 = ex0 ? pt0 : pt0 * i0;
            pt1 = ex1 ? pt1 : pt1 * i1;
            pt2 = ex2 ? pt2 : pt2 * i2;
            pt3 = ex3 ? pt3 : pt3 * i3;
            *reinterpret_cast<float4*>(yp + (size_t)j * Cc) = r;
        }
    }
}

// ---------------------------------------------------------------------------
// Kernel 3: tf32 tensor-core GEMM via mma.sync + ldmatrix (round-9 config:
// measured 107.7us @ 57.1% tensor). out = y @ W^T + bias.
// CTA tile 128x128x32, 256 threads (8 warps 4m x 2n, warp tile 32x64),
// 2 CTAs/SM, 3-stage cp.async pipeline, LDSM.x4 loads, pitch 36.
// ---------------------------------------------------------------------------
#define BM 128
#define BN 128
#define KC 32
#define NCHK (Cc / KC)           // 16
#define PITCH 36                 // floats per smem row
#define A_ST_FLOATS (BM * PITCH) // 4608
#define B_ST_FLOATS (BN * PITCH) // 4608
#define STAGE_FLOATS (A_ST_FLOATS + B_ST_FLOATS)  // 9216
#define NSTAGE 3
#define SMEM_TOTAL (NSTAGE * STAGE_FLOATS * 4)    // 110592 B

__device__ __forceinline__ void mma_tf32(float* d, const uint32_t* a, const uint32_t* b) {
    asm volatile(
        "mma.sync.aligned.m16n8k8.row.col.f32.tf32.tf32.f32 "
        "{%0,%1,%2,%3}, {%4,%5,%6,%7}, {%8,%9}, {%0,%1,%2,%3};"
        : "+f"(d[0]), "+f"(d[1]), "+f"(d[2]), "+f"(d[3])
        : "r"(a[0]), "r"(a[1]), "r"(a[2]), "r"(a[3]), "r"(b[0]), "r"(b[1]));
}

__device__ __forceinline__ void ldsm_x4(uint32_t* r, uint32_t saddr) {
    asm volatile(
        "ldmatrix.sync.aligned.m8n8.x4.shared.b16 {%0,%1,%2,%3}, [%4];"
        : "=r"(r[0]), "=r"(r[1]), "=r"(r[2]), "=r"(r[3]) : "r"(saddr));
}

__global__ void __launch_bounds__(256, 2) gemm_mma_kernel(
    const float* __restrict__ bias, float* __restrict__ out)
{
    extern __shared__ __align__(128) float smem[];

    const int tid = threadIdx.x;
    const int wid = tid >> 5;
    const int lane = tid & 31;
    const int q = lane >> 2;   // 0..7
    const int cq = lane & 3;   // 0..3

    const int bm = blockIdx.x >> 2;   // 0..255
    const int bn = blockIdx.x & 3;    // 0..3
    const int wm = wid >> 1;          // 0..3  (32-row blocks)
    const int wn = wid & 1;           // 0..1  (64-col blocks)

    const float* Abase = g_y + (size_t)(bm * BM) * Cc;
    const float* Bbase = g_W + (size_t)(bn * BN) * Cc;

    const uint32_t smemS = (uint32_t)__cvta_generic_to_shared(smem);

    // ldmatrix per-lane addresses (A: {(m0,k8),(m0+8,k8),(m0,k8+4),(m0+8,k8+4)};
    //  B pair p: {(n0,k8),(n0,k8+4),(n0+8,k8),(n0+8,k8+4)})
    const int rowA = (lane & 7) + ((lane >> 3) & 1) * 8;
    const int colA = (lane >> 4) * 4;
    const int rowB = (lane & 7) + (lane >> 4) * 8;
    const int colB = ((lane >> 3) & 1) * 4;

    const uint32_t aLane = (uint32_t)(((wm * 32 + rowA) * PITCH + colA) * 4);
    const uint32_t bLane = (uint32_t)((A_ST_FLOATS + (wn * 64 + rowB) * PITCH + colB) * 4);

    // cp.async issue helper: 2048 16B-segments per chunk (A:1024, B:1024)
    auto issue_chunk = [&](int ch) {
        float* stg = smem + (ch % NSTAGE) * STAGE_FLOATS;
        const int kof = ch * KC;
#pragma unroll
        for (int i = 0; i < 8; ++i) {
            const int u = tid + i * 256;
            const float* src;
            float* dst;
            if (u < 1024) {
                const int row = u >> 3, seg = u & 7;
                src = Abase + (size_t)row * Cc + kof + seg * 4;
                dst = stg + row * PITCH + seg * 4;
            } else {
                const int v = u - 1024;
                const int row = v >> 3, seg = v & 7;
                src = Bbase + (size_t)row * Cc + kof + seg * 4;
                dst = stg + A_ST_FLOATS + row * PITCH + seg * 4;
            }
            uint32_t daddr = (uint32_t)__cvta_generic_to_shared(dst);
            asm volatile("cp.async.cg.shared.global [%0], [%1], 16;"
                         :: "r"(daddr), "l"(src) : "memory");
        }
        asm volatile("cp.async.commit_group;" ::: "memory");
    };

    // Prologue: chunks 0,1
    issue_chunk(0);
    issue_chunk(1);

    float acc[2][8][4];
#pragma unroll
    for (int mt = 0; mt < 2; ++mt)
#pragma unroll
        for (int nt = 0; nt < 8; ++nt)
#pragma unroll
            for (int e = 0; e < 4; ++e) acc[mt][nt][e] = 0.f;

#pragma unroll 1
    for (int ch = 0; ch < NCHK; ++ch) {
        if (ch < NCHK - 1) {
            asm volatile("cp.async.wait_group 1;" ::: "memory");
        } else {
            asm volatile("cp.async.wait_group 0;" ::: "memory");
        }
        __syncthreads();   // chunk ch visible; compute(ch-1) done by all

        if (ch + 2 < NCHK) issue_chunk(ch + 2);

        const uint32_t stS = smemS + (uint32_t)((ch % NSTAGE) * STAGE_FLOATS * 4);
        const uint32_t aBase = stS + aLane;
        const uint32_t bBase = stS + bLane;

#pragma unroll
        for (int ks = 0; ks < 4; ++ks) {
            const uint32_t ko = (uint32_t)(ks * 8 * 4);
            uint32_t a[2][4], b[8][2];
#pragma unroll
            for (int mt = 0; mt < 2; ++mt)
                ldsm_x4(a[mt], aBase + (uint32_t)(mt * 16 * PITCH * 4) + ko);
#pragma unroll
            for (int p = 0; p < 4; ++p)
                ldsm_x4(&b[2 * p][0], bBase + (uint32_t)(p * 16 * PITCH * 4) + ko);
#pragma unroll
            for (int mt = 0; mt < 2; ++mt)
#pragma unroll
                for (int nt = 0; nt < 8; ++nt)
                    mma_tf32(acc[mt][nt], a[mt], b[nt]);
        }
    }

    // Epilogue: bias + store
#pragma unroll
    for (int nt = 0; nt < 8; ++nt) {
        const int col = bn * BN + wn * 64 + nt * 8 + cq * 2;
        const float b0 = __ldg(bias + col);
        const float b1 = __ldg(bias + col + 1);
#pragma unroll
        for (int mt = 0; mt < 2; ++mt) {
            const size_t row0 = (size_t)(bm * BM + wm * 32 + mt * 16 + q);
            float2 v0, v1;
            v0.x = acc[mt][nt][0] + b0; v0.y = acc[mt][nt][1] + b1;
            v1.x = acc[mt][nt][2] + b0; v1.y = acc[mt][nt][3] + b1;
            *reinterpret_cast<float2*>(out + row0 * Cc + col) = v0;
            *reinterpret_cast<float2*>(out + (row0 + 8) * Cc + col) = v1;
        }
    }
}

// ---------------------------------------------------------------------------
extern "C" void kernel_launch(void* const* d_in, const int* in_sizes, int n_in,
                              void* d_out, int out_size)
{
    (void)in_sizes; (void)n_in; (void)out_size;
    const float* x    = (const float*)d_in[0];
    const float* logd = (const float*)d_in[1];
    const float* mixw = (const float*)d_in[2];
    const float* bias = (const float*)d_in[3];
    float* out = (float*)d_out;

    cudaFuncSetAttribute(gemm_mma_kernel, cudaFuncAttributeMaxDynamicSharedMemorySize,
                         SMEM_TOTAL);

    chunk_sum_kernel<<<Bb * NCHUNK, 128>>>(x, logd, mixw);
    prefix_kernel<<<32, 128>>>();
    apply_kernel<<<Bb * NCHUNK, 128>>>(x, logd);
    gemm_mma_kernel<<<1024, 256, SMEM_TOTAL>>>(bias, out);
}

// round 17
// speedup vs baseline: 1.4268x; 1.2971x over previous
#include <cuda_runtime.h>
#include <cuda_fp16.h>
#include <cstdint>
#include <math.h>

// Problem dims
#define Bb 8
#define Tt 4096
#define Cc 512
#define NCHUNK 256
#define LCHUNK 16   // Tt / NCHUNK

// Scratch (device globals: no runtime allocation allowed)
__device__ __align__(256) __half g_yh[Bb * Tt * Cc];    // 32 MB intermediate y (fp16)
__device__ __align__(256) float  g_A[Bb * NCHUNK * Cc]; // chunk sums -> exclusive prefix
__device__ __align__(256) __half g_Wh[Cc * Cc];         // fp16 weights

// ---------------------------------------------------------------------------
// Kernel 1: per-chunk absolutely-weighted sums  A[b,k,c] = sum_j d^(t0+j) x
// First 512 blocks also convert one float4 of W to fp16 per thread.
// ---------------------------------------------------------------------------
__global__ void __launch_bounds__(128) chunk_sum_kernel(
    const float* __restrict__ x, const float* __restrict__ logd,
    const float* __restrict__ W)
{
    const int b = blockIdx.x / NCHUNK;
    const int k = blockIdx.x % NCHUNK;
    const int c = threadIdx.x * 4;

    if (blockIdx.x < 512) {
        const int i = (blockIdx.x * 128 + threadIdx.x) * 4;
        float4 v = *reinterpret_cast<const float4*>(W + i);
        __half2 h0 = __floats2half2_rn(v.x, v.y);
        __half2 h1 = __floats2half2_rn(v.z, v.w);
        uint2 u;
        u.x = *reinterpret_cast<uint32_t*>(&h0);
        u.y = *reinterpret_cast<uint32_t*>(&h1);
        *reinterpret_cast<uint2*>(&g_Wh[i]) = u;
    }

    float4 ld4 = *reinterpret_cast<const float4*>(logd + c);
    const float d0 = 1.0f / (1.0f + expf(-ld4.x));
    const float d1 = 1.0f / (1.0f + expf(-ld4.y));
    const float d2 = 1.0f / (1.0f + expf(-ld4.z));
    const float d3 = 1.0f / (1.0f + expf(-ld4.w));

    const float ft0 = (float)(k * LCHUNK);
    float w0 = exp2f(ft0 * log2f(d0));
    float w1 = exp2f(ft0 * log2f(d1));
    float w2 = exp2f(ft0 * log2f(d2));
    float w3 = exp2f(ft0 * log2f(d3));

    const float* xp = x + ((size_t)b * Tt + (size_t)k * LCHUNK) * Cc + c;

    float a0 = 0.f, a1 = 0.f, a2 = 0.f, a3 = 0.f;
#pragma unroll
    for (int j = 0; j < LCHUNK; ++j) {
        float4 v = *reinterpret_cast<const float4*>(xp + (size_t)j * Cc);
        a0 += w0 * v.x;
        a1 += w1 * v.y;
        a2 += w2 * v.z;
        a3 += w3 * v.w;
        w0 *= d0; w1 *= d1; w2 *= d2; w3 *= d3;
    }

    float4 r; r.x = a0; r.y = a1; r.z = a2; r.w = a3;
    *reinterpret_cast<float4*>(&g_A[((size_t)b * NCHUNK + k) * Cc + c]) = r;
}

// ---------------------------------------------------------------------------
// Kernel 1b: in-place exclusive prefix over chunks of g_A.
// ---------------------------------------------------------------------------
__global__ void __launch_bounds__(128) prefix_kernel()
{
    const int gid = blockIdx.x * 128 + threadIdx.x;  // 0..4095
    const int b = gid >> 9;
    const int c = gid & 511;
    float* Ap = g_A + (size_t)b * NCHUNK * Cc + c;
    float P = 0.f;
#pragma unroll 8
    for (int k = 0; k < NCHUNK; ++k) {
        const float v = Ap[(size_t)k * Cc];
        Ap[(size_t)k * Cc] = P;
        P += v;
    }
}

// ---------------------------------------------------------------------------
// Kernel 2: local rescan; y = d^(T-1-t) * (P + local sum), stored as fp16.
// ---------------------------------------------------------------------------
__global__ void __launch_bounds__(128) apply_kernel(
    const float* __restrict__ x, const float* __restrict__ logd)
{
    const int b = blockIdx.x / NCHUNK;
    const int k = blockIdx.x % NCHUNK;
    const int c = threadIdx.x * 4;

    float4 ld4 = *reinterpret_cast<const float4*>(logd + c);
    const float d0 = 1.0f / (1.0f + expf(-ld4.x));
    const float d1 = 1.0f / (1.0f + expf(-ld4.y));
    const float d2 = 1.0f / (1.0f + expf(-ld4.z));
    const float d3 = 1.0f / (1.0f + expf(-ld4.w));
    const float l20 = log2f(d0), l21 = log2f(d1), l22 = log2f(d2), l23 = log2f(d3);

    const float4 Pv = *reinterpret_cast<const float4*>(
        g_A + ((size_t)b * NCHUNK + k) * Cc + c);

    const int t0 = k * LCHUNK;
    const float ft0 = (float)t0;
    float w0 = exp2f(ft0 * l20);
    float w1 = exp2f(ft0 * l21);
    float w2 = exp2f(ft0 * l22);
    float w3 = exp2f(ft0 * l23);

    const float eb0 = (float)(Tt - 1 - t0) * l20;
    const float eb1 = (float)(Tt - 1 - t0) * l21;
    const float eb2 = (float)(Tt - 1 - t0) * l22;
    const float eb3 = (float)(Tt - 1 - t0) * l23;
    const float ee0 = (float)(Tt - 1 - t0 - (LCHUNK - 1)) * l20;
    const float ee1 = (float)(Tt - 1 - t0 - (LCHUNK - 1)) * l21;
    const float ee2 = (float)(Tt - 1 - t0 - (LCHUNK - 1)) * l22;
    const float ee3 = (float)(Tt - 1 - t0 - (LCHUNK - 1)) * l23;
    const bool ex0 = (eb0 < -100.f) && (ee0 > -140.f);
    const bool ex1 = (eb1 < -100.f) && (ee1 > -140.f);
    const bool ex2 = (eb2 < -100.f) && (ee2 > -140.f);
    const bool ex3 = (eb3 < -100.f) && (ee3 > -140.f);
    const bool anyex = ex0 | ex1 | ex2 | ex3;

    float pt0 = exp2f(eb0), pt1 = exp2f(eb1), pt2 = exp2f(eb2), pt3 = exp2f(eb3);
    const float i0 = 1.0f / d0, i1 = 1.0f / d1, i2 = 1.0f / d2, i3 = 1.0f / d3;

    float S0 = Pv.x, S1 = Pv.y, S2 = Pv.z, S3 = Pv.w;

    const float* xp = x + ((size_t)b * Tt + t0) * Cc + c;
    __half* yp = g_yh + ((size_t)b * Tt + t0) * Cc + c;

    if (!anyex) {
#pragma unroll
        for (int j = 0; j < LCHUNK; ++j) {
            float4 v = *reinterpret_cast<const float4*>(xp + (size_t)j * Cc);
            S0 += w0 * v.x; w0 *= d0;
            S1 += w1 * v.y; w1 *= d1;
            S2 += w2 * v.z; w2 *= d2;
            S3 += w3 * v.w; w3 *= d3;
            __half2 h0 = __floats2half2_rn(pt0 * S0, pt1 * S1);
            __half2 h1 = __floats2half2_rn(pt2 * S2, pt3 * S3);
            uint2 u;
            u.x = *reinterpret_cast<uint32_t*>(&h0);
            u.y = *reinterpret_cast<uint32_t*>(&h1);
            pt0 *= i0; pt1 *= i1; pt2 *= i2; pt3 *= i3;
            *reinterpret_cast<uint2*>(yp + (size_t)j * Cc) = u;
        }
    } else {
        for (int j = 0; j < LCHUNK; ++j) {
            const float tj = (float)(Tt - 1 - t0 - j);
            pt0 = ex0 ? exp2f(tj * l20) : pt0;
            pt1 = ex1 ? exp2f(tj * l21) : pt1;
            pt2 = ex2 ? exp2f(tj * l22) : pt2;
            pt3 = ex3 ? exp2f(tj * l23) : pt3;
            float4 v = *reinterpret_cast<const float4*>(xp + (size_t)j * Cc);
            S0 += w0 * v.x; w0 *= d0;
            S1 += w1 * v.y; w1 *= d1;
            S2 += w2 * v.z; w2 *= d2;
            S3 += w3 * v.w; w3 *= d3;
            __half2 h0 = __floats2half2_rn(pt0 * S0, pt1 * S1);
            __half2 h1 = __floats2half2_rn(pt2 * S2, pt3 * S3);
            uint2 u;
            u.x = *reinterpret_cast<uint32_t*>(&h0);
            u.y = *reinterpret_cast<uint32_t*>(&h1);
            pt0 = ex0 ? pt0 : pt0 * i0;
            pt1 = ex1 ? pt1 : pt1 * i1;
            pt2 = ex2 ? pt2 : pt2 * i2;
            pt3 = ex3 ? pt3 : pt3 * i3;
            *reinterpret_cast<uint2*>(yp + (size_t)j * Cc) = u;
        }
    }
}

// ---------------------------------------------------------------------------
// Kernel 3: fp16 tensor-core GEMM via mma.sync.m16n8k16 + ldmatrix.
// out = y @ W^T + bias. CTA tile 128x128x32, 256 threads (8 warps 4m x 2n,
// warp tile 32x64), 2 CTAs/SM, 4-stage cp.async pipeline, pitch 40 halfs
// (80B rows -> conflict-free ldmatrix).
// ---------------------------------------------------------------------------
#define BM 128
#define BN 128
#define KC 32
#define NCHK (Cc / KC)             // 16
#define PITCH_H 40                 // halfs per smem row (32 + 8 pad)
#define A_ST_HALF (BM * PITCH_H)   // 5120
#define B_ST_HALF (BN * PITCH_H)   // 5120
#define STAGE_HALF (A_ST_HALF + B_ST_HALF)   // 10240 halfs = 20480 B
#define NSTAGE 4
#define SMEM_TOTAL (NSTAGE * STAGE_HALF * 2) // 81920 B

__device__ __forceinline__ void mma_f16(float* d, const uint32_t* a, const uint32_t* b) {
    asm volatile(
        "mma.sync.aligned.m16n8k16.row.col.f32.f16.f16.f32 "
        "{%0,%1,%2,%3}, {%4,%5,%6,%7}, {%8,%9}, {%0,%1,%2,%3};"
        : "+f"(d[0]), "+f"(d[1]), "+f"(d[2]), "+f"(d[3])
        : "r"(a[0]), "r"(a[1]), "r"(a[2]), "r"(a[3]), "r"(b[0]), "r"(b[1]));
}

__device__ __forceinline__ void ldsm_x4(uint32_t* r, uint32_t saddr) {
    asm volatile(
        "ldmatrix.sync.aligned.m8n8.x4.shared.b16 {%0,%1,%2,%3}, [%4];"
        : "=r"(r[0]), "=r"(r[1]), "=r"(r[2]), "=r"(r[3]) : "r"(saddr));
}

__global__ void __launch_bounds__(256, 2) gemm_mma_kernel(
    const float* __restrict__ bias, float* __restrict__ out)
{
    extern __shared__ __align__(128) __half smem[];

    const int tid = threadIdx.x;
    const int wid = tid >> 5;
    const int lane = tid & 31;
    const int q = lane >> 2;   // 0..7
    const int cq = lane & 3;   // 0..3

    const int bm = blockIdx.x >> 2;   // 0..255
    const int bn = blockIdx.x & 3;    // 0..3
    const int wm = wid >> 1;          // 0..3  (32-row blocks)
    const int wn = wid & 1;           // 0..1  (64-col blocks)

    const __half* Abase = g_yh + (size_t)(bm * BM) * Cc;
    const __half* Bbase = g_Wh + (size_t)(bn * BN) * Cc;

    const uint32_t smemS = (uint32_t)__cvta_generic_to_shared(smem);

    // ldmatrix per-lane addresses.
    // A 16x16 tile: matrices {(r0-7,k0-7),(r8-15,k0-7),(r0-7,k8-15),(r8-15,k8-15)}
    const int rowA = (lane & 7) + ((lane >> 3) & 1) * 8;
    const int colAh = (lane >> 4) * 8;   // halfs (16B)
    // B (stored [n][k]) pair p: {(n0-7,k0-7),(n0-7,k8-15),(n8-15,k0-7),(n8-15,k8-15)}
    const int rowB = (lane & 7) + (lane >> 4) * 8;
    const int colBh = ((lane >> 3) & 1) * 8;

    const uint32_t aLane = (uint32_t)(((wm * 32 + rowA) * PITCH_H + colAh) * 2);
    const uint32_t bLane = (uint32_t)((A_ST_HALF + (wn * 64 + rowB) * PITCH_H + colBh) * 2);

    // cp.async: 1024 16B-segments per chunk (A:512, B:512), 4 per thread
    auto issue_chunk = [&](int ch) {
        __half* stg = smem + (ch % NSTAGE) * STAGE_HALF;
        const int kof = ch * KC;
#pragma unroll
        for (int i = 0; i < 4; ++i) {
            const int u = tid + i * 256;
            const __half* src;
            __half* dst;
            if (u < 512) {
                const int row = u >> 2, seg = u & 3;
                src = Abase + (size_t)row * Cc + kof + seg * 8;
                dst = stg + row * PITCH_H + seg * 8;
            } else {
                const int v = u - 512;
                const int row = v >> 2, seg = v & 3;
                src = Bbase + (size_t)row * Cc + kof + seg * 8;
                dst = stg + A_ST_HALF + row * PITCH_H + seg * 8;
            }
            uint32_t daddr = (uint32_t)__cvta_generic_to_shared(dst);
            asm volatile("cp.async.cg.shared.global [%0], [%1], 16;"
                         :: "r"(daddr), "l"(src) : "memory");
        }
        asm volatile("cp.async.commit_group;" ::: "memory");
    };

    // Prologue: chunks 0,1,2
    issue_chunk(0);
    issue_chunk(1);
    issue_chunk(2);

    float acc[2][8][4];
#pragma unroll
    for (int mt = 0; mt < 2; ++mt)
#pragma unroll
        for (int nt = 0; nt < 8; ++nt)
#pragma unroll
            for (int e = 0; e < 4; ++e) acc[mt][nt][e] = 0.f;

#pragma unroll 1
    for (int ch = 0; ch < NCHK; ++ch) {
        if (ch < NCHK - 2) {
            asm volatile("cp.async.wait_group 2;" ::: "memory");
        } else if (ch == NCHK - 2) {
            asm volatile("cp.async.wait_group 1;" ::: "memory");
        } else {
            asm volatile("cp.async.wait_group 0;" ::: "memory");
        }
        __syncthreads();   // chunk ch visible; compute(ch-1) done by all

        if (ch + 3 < NCHK) issue_chunk(ch + 3);

        const uint32_t stS = smemS + (uint32_t)((ch % NSTAGE) * STAGE_HALF * 2);
        const uint32_t aBase = stS + aLane;
        const uint32_t bBase = stS + bLane;

#pragma unroll
        for (int ks = 0; ks < 2; ++ks) {
            const uint32_t ko = (uint32_t)(ks * 32);   // 16 halfs = 32 B
            uint32_t a[2][4], b[8][2];
#pragma unroll
            for (int mt = 0; mt < 2; ++mt)
                ldsm_x4(a[mt], aBase + (uint32_t)(mt * 16 * PITCH_H * 2) + ko);
#pragma unroll
            for (int p = 0; p < 4; ++p)
                ldsm_x4(&b[2 * p][0], bBase + (uint32_t)(p * 16 * PITCH_H * 2) + ko);
#pragma unroll
            for (int mt = 0; mt < 2; ++mt)
#pragma unroll
                for (int nt = 0; nt < 8; ++nt)
                    mma_f16(acc[mt][nt], a[mt], b[nt]);
        }
    }

    // Epilogue: bias + store
#pragma unroll
    for (int nt = 0; nt < 8; ++nt) {
        const int col = bn * BN + wn * 64 + nt * 8 + cq * 2;
        const float b0 = __ldg(bias + col);
        const float b1 = __ldg(bias + col + 1);
#pragma unroll
        for (int mt = 0; mt < 2; ++mt) {
            const size_t row0 = (size_t)(bm * BM + wm * 32 + mt * 16 + q);
            float2 v0, v1;
            v0.x = acc[mt][nt][0] + b0; v0.y = acc[mt][nt][1] + b1;
            v1.x = acc[mt][nt][2] + b0; v1.y = acc[mt][nt][3] + b1;
            *reinterpret_cast<float2*>(out + row0 * Cc + col) = v0;
            *reinterpret_cast<float2*>(out + (row0 + 8) * Cc + col) = v1;
        }
    }
}

// ---------------------------------------------------------------------------
extern "C" void kernel_launch(void* const* d_in, const int* in_sizes, int n_in,
                              void* d_out, int out_size)
{
    (void)in_sizes; (void)n_in; (void)out_size;
    const float* x    = (const float*)d_in[0];
    const float* logd = (const float*)d_in[1];
    const float* mixw = (const float*)d_in[2];
    const float* bias = (const float*)d_in[3];
    float* out = (float*)d_out;

    cudaFuncSetAttribute(gemm_mma_kernel, cudaFuncAttributeMaxDynamicSharedMemorySize,
                         SMEM_TOTAL);

    chunk_sum_kernel<<<Bb * NCHUNK, 128>>>(x, logd, mixw);
    prefix_kernel<<<32, 128>>>();
    apply_kernel<<<Bb * NCHUNK, 128>>>(x, logd);
    gemm_mma_kernel<<<1024, 256, SMEM_TOTAL>>>(bias, out);
}